// round 11
// baseline (speedup 1.0000x reference)
#include <cuda_runtime.h>
#include <cuda_bf16.h>
#include <cuda_fp16.h>
#include <cstdint>

// ============================================================================
// Problem constants
// ============================================================================
#define NB     16384
#define NNODE  12
#define CDIM   512
#define SXLD   (CDIM + 4)      // padded smem row (bank-conflict fix)
#define ROWS   (NB * NNODE)
#define KDIM   1024
#define NDIM   512
#define TOPK   4
#define BN_EPS 1e-5f

// ============================================================================
// Helpers (baseline PTX only)
// ============================================================================
__device__ __forceinline__ uint32_t smem_u32(const void* p) {
    uint32_t a;
    asm("{ .reg .u64 t; cvta.to.shared.u64 t, %1; cvt.u32.u64 %0, t; }" : "=r"(a) : "l"(p));
    return a;
}
__device__ __forceinline__ void ldsm_x4(uint32_t* r, uint32_t addr) {
    asm volatile("ldmatrix.sync.aligned.m8n8.x4.shared.b16 {%0,%1,%2,%3}, [%4];"
                 : "=r"(r[0]), "=r"(r[1]), "=r"(r[2]), "=r"(r[3]) : "r"(addr));
}
__device__ __forceinline__ void ldsm_x2(uint32_t* r, uint32_t addr) {
    asm volatile("ldmatrix.sync.aligned.m8n8.x2.shared.b16 {%0,%1}, [%2];"
                 : "=r"(r[0]), "=r"(r[1]) : "r"(addr));
}
__device__ __forceinline__ void cp_async16(uint32_t saddr, const void* gaddr) {
    asm volatile("cp.async.cg.shared.global [%0], [%1], 16;" :: "r"(saddr), "l"(gaddr));
}
#define CP_COMMIT() asm volatile("cp.async.commit_group;" ::: "memory")
#define CP_WAIT1()  asm volatile("cp.async.wait_group 1;" ::: "memory")

__device__ __forceinline__ void mma_bf16(float* d, const uint32_t* a, const uint32_t* b) {
    asm volatile(
        "mma.sync.aligned.m16n8k16.row.col.f32.bf16.bf16.f32 "
        "{%0,%1,%2,%3}, {%4,%5,%6,%7}, {%8,%9}, {%0,%1,%2,%3};"
        : "+f"(d[0]), "+f"(d[1]), "+f"(d[2]), "+f"(d[3])
        : "r"(a[0]), "r"(a[1]), "r"(a[2]), "r"(a[3]), "r"(b[0]), "r"(b[1]));
}
__device__ __forceinline__ uint32_t pack_hi2(float a, float b) {
    __nv_bfloat162 t;
    t.x = __float2bfloat16(a);
    t.y = __float2bfloat16(b);
    return *reinterpret_cast<uint32_t*>(&t);
}
__device__ __forceinline__ uint32_t pack_lo2(float a, float b) {
    __nv_bfloat162 t;
    __nv_bfloat16 ha = __float2bfloat16(a);
    __nv_bfloat16 hb = __float2bfloat16(b);
    t.x = __float2bfloat16(a - __bfloat162float(ha));
    t.y = __float2bfloat16(b - __bfloat162float(hb));
    return *reinterpret_cast<uint32_t*>(&t);
}

// ============================================================================
// Device scratch  (h stored as fp16: halves h traffic; stats stay fp32)
// ============================================================================
__device__ __align__(16) __nv_bfloat16 g_ahi[(size_t)ROWS * KDIM];
__device__ __align__(16) __nv_bfloat16 g_alo[(size_t)ROWS * KDIM];
__device__ __align__(16) __nv_bfloat16 g_whi[(size_t)NDIM * KDIM];
__device__ __align__(16) __nv_bfloat16 g_wlo[(size_t)NDIM * KDIM];
__device__ __align__(16) __half g_h[(size_t)ROWS * CDIM];
__device__ float g_rs[ROWS];
__device__ float g_sum[NNODE];
__device__ float g_sumsq[NNODE];
__device__ float g_scale[NNODE];
__device__ float g_shift[NNODE];

// ============================================================================
// Kernel 0a
// ============================================================================
__global__ void k_zero_stats() {
    int t = threadIdx.x;
    if (t < NNODE) { g_sum[t] = 0.f; g_sumsq[t] = 0.f; }
}

// ============================================================================
// Kernel 0b: pack W = [Vw | Uw] as bf16 hi/lo
// ============================================================================
__global__ void k_prep_w(const float* __restrict__ Uw, const float* __restrict__ Vw) {
    int idx = blockIdx.x * blockDim.x + threadIdx.x;
    if (idx >= NDIM * KDIM) return;
    int d = idx >> 10;
    int k = idx & 1023;
    float v = (k < 512) ? Vw[d * 512 + k] : Uw[d * 512 + (k - 512)];
    __nv_bfloat16 hi = __float2bfloat16(v);
    float lo = v - __bfloat162float(hi);
    g_whi[idx] = hi;
    g_wlo[idx] = __float2bfloat16(lo);
}

// ============================================================================
// Kernel 1: adjacency + aggregation -> A-operand rows [y | x] (hi/lo)
// ============================================================================
__global__ __launch_bounds__(128) void k_adjacency(const float* __restrict__ x) {
    __shared__ __align__(16) float sx[NNODE][SXLD];
    __shared__ float ssim[NNODE][NNODE];
    __shared__ float sA[NNODE][NNODE];
    __shared__ float sthr[NNODE];
    __shared__ float sdinv[NNODE];

    const int tid = threadIdx.x;
    const int b   = blockIdx.x;

    {
        const float4* src = reinterpret_cast<const float4*>(x + (size_t)b * NNODE * CDIM);
        for (int u = tid; u < NNODE * CDIM / 4; u += 128) {
            int i = u >> 7;
            int q = u & 127;
            *reinterpret_cast<float4*>(&sx[i][q * 4]) = src[u];
        }
    }
    __syncthreads();

    if (tid < 78) {
        int i = 0, t = tid;
        while (t >= NNODE - i) { t -= NNODE - i; i++; }
        int j = i + t;
        float a0 = 0.f, a1 = 0.f, a2 = 0.f, a3 = 0.f;
        #pragma unroll 4
        for (int c = 0; c < CDIM; c += 4) {
            float4 a  = *reinterpret_cast<const float4*>(&sx[i][c]);
            float4 bb = *reinterpret_cast<const float4*>(&sx[j][c]);
            a0 += a.x * bb.x; a1 += a.y * bb.y;
            a2 += a.z * bb.z; a3 += a.w * bb.w;
        }
        float acc = (a0 + a1) + (a2 + a3);
        ssim[i][j] = acc;
        ssim[j][i] = acc;
    }
    __syncthreads();

    if (tid < NNODE) {
        float v[NNODE];
        #pragma unroll
        for (int j = 0; j < NNODE; j++) v[j] = ssim[tid][j];
        float thr = 0.f;
        #pragma unroll
        for (int t = 0; t < TOPK; t++) {
            int m = 0;
            float mv = v[0];
            #pragma unroll
            for (int j = 1; j < NNODE; j++) if (v[j] > mv) { mv = v[j]; m = j; }
            thr = mv;
            v[m] = -3.4e38f;
        }
        sthr[tid] = thr;
        int deg = 0;
        #pragma unroll
        for (int j = 0; j < NNODE; j++) deg += (ssim[tid][j] >= thr) ? 1 : 0;
        sdinv[tid] = rsqrtf((float)deg);
    }
    __syncthreads();

    for (int t = tid; t < NNODE * NNODE; t += 128) {
        int i = t / NNODE, j = t % NNODE;
        float adj = (ssim[i][j] >= sthr[i]) ? 1.f : 0.f;
        sA[i][j] = sdinv[i] * sdinv[j] * adj;
    }
    __syncthreads();

    if (tid < NNODE) {
        float rs = 0.f;
        #pragma unroll
        for (int j = 0; j < NNODE; j++) rs += sA[tid][j];
        g_rs[(size_t)b * NNODE + tid] = rs;
    }

    // y = A @ x -> cols [0,512)
    {
        const int c0 = tid * 4;
        float4 xv[NNODE];
        #pragma unroll
        for (int j = 0; j < NNODE; j++)
            xv[j] = *reinterpret_cast<const float4*>(&sx[j][c0]);
        #pragma unroll
        for (int i = 0; i < NNODE; i++) {
            float a0 = 0.f, a1 = 0.f, a2 = 0.f, a3 = 0.f;
            #pragma unroll
            for (int j = 0; j < NNODE; j++) {
                float w = sA[i][j];
                a0 += w * xv[j].x; a1 += w * xv[j].y;
                a2 += w * xv[j].z; a3 += w * xv[j].w;
            }
            size_t o = ((size_t)b * NNODE + i) * KDIM + c0;
            uint2 hi = make_uint2(pack_hi2(a0, a1), pack_hi2(a2, a3));
            uint2 lo = make_uint2(pack_lo2(a0, a1), pack_lo2(a2, a3));
            *reinterpret_cast<uint2*>(g_ahi + o) = hi;
            *reinterpret_cast<uint2*>(g_alo + o) = lo;
        }
    }

    // x -> cols [512,1024)
    for (int u = tid; u < NNODE * 128; u += 128) {
        int i = u >> 7, q = u & 127;
        float4 v = *reinterpret_cast<const float4*>(&sx[i][q * 4]);
        size_t o = ((size_t)b * NNODE + i) * KDIM + 512 + q * 4;
        uint2 hi = make_uint2(pack_hi2(v.x, v.y), pack_hi2(v.z, v.w));
        uint2 lo = make_uint2(pack_lo2(v.x, v.y), pack_lo2(v.z, v.w));
        *reinterpret_cast<uint2*>(g_ahi + o) = hi;
        *reinterpret_cast<uint2*>(g_alo + o) = lo;
    }
}

// ============================================================================
// Kernel 2: GEMM  h = [y|x] @ Wcat^T + rs*Vb + Ub   (bf16x3, HMMA, ldmatrix)
// R7/R10 structure + WARP DE-PHASING: warps traverse (ks,g) in wid-dependent
// order so the 4 phase-groups' LDSM bursts overlap other groups' MMA batches
// (accumulation order is irrelevant to correctness).
// ============================================================================
#define LDA        40
#define TILE_B     (128 * LDA)
#define STAGE_E    (4 * TILE_B)
#define STAGE_BYTES (STAGE_E * 2)          // 40960
#define SMEM2_BYTES (2 * STAGE_BYTES)      // 81920

__device__ __forceinline__ void issue_chunk(uint32_t sbase, int mrow0, int n0,
                                            int kc, int arow, int acol) {
    const size_t ga = (size_t)(mrow0 + arow) * KDIM + kc * 32 + acol;
    const size_t gw = (size_t)(n0 + arow) * KDIM + kc * 32 + acol;
    const uint32_t off = (uint32_t)(arow * LDA + acol) * 2;
    cp_async16(sbase + off,                     g_ahi + ga);
    cp_async16(sbase + off + 16,                g_ahi + ga + 8);
    cp_async16(sbase + TILE_B * 2 + off,        g_alo + ga);
    cp_async16(sbase + TILE_B * 2 + off + 16,   g_alo + ga + 8);
    cp_async16(sbase + 2 * TILE_B * 2 + off,      g_whi + gw);
    cp_async16(sbase + 2 * TILE_B * 2 + off + 16, g_whi + gw + 8);
    cp_async16(sbase + 3 * TILE_B * 2 + off,      g_wlo + gw);
    cp_async16(sbase + 3 * TILE_B * 2 + off + 16, g_wlo + gw + 8);
}

__global__ __launch_bounds__(256, 2) void k_gemm(const float* __restrict__ Vb,
                                                 const float* __restrict__ Ub) {
    extern __shared__ __align__(128) __nv_bfloat16 sm[];
    __shared__ float sBias[256];
    __shared__ float sred[24];

    const int tid  = threadIdx.x;
    const int wid  = tid >> 5;
    const int lane = tid & 31;

    const int ntile = blockIdx.x & 3;
    const int mtile = blockIdx.x >> 2;
    const int mrow0 = mtile * 128;
    const int n0    = ntile * 128;

    const int wm = (wid & 3) * 32;
    const int wn = (wid >> 2) * 64;
    const int ks_xor = (wid >> 1) & 1;     // de-phase ks order per warp-pair
    const int g_xor  = wid & 1;            // de-phase g order per warp

    for (int i = tid; i < 128; i += 256) {
        sBias[i]       = Vb[n0 + i];
        sBias[128 + i] = Ub[n0 + i];
    }
    if (tid < 24) sred[tid] = 0.f;

    float acc[2][8][4];
    #pragma unroll
    for (int mi = 0; mi < 2; mi++)
        #pragma unroll
        for (int nb = 0; nb < 8; nb++)
            #pragma unroll
            for (int q = 0; q < 4; q++) acc[mi][nb][q] = 0.f;

    const int arow = tid >> 1;
    const int acol = (tid & 1) * 16;
    const uint32_t sm_addr = smem_u32(sm);

    issue_chunk(sm_addr, mrow0, n0, 0, arow, acol);
    CP_COMMIT();
    issue_chunk(sm_addr + STAGE_BYTES, mrow0, n0, 1, arow, acol);
    CP_COMMIT();

    #pragma unroll 1
    for (int kc = 0; kc < 32; kc++) {
        CP_WAIT1();
        __syncthreads();

        {
            const uint32_t sA_hi = sm_addr + (uint32_t)(kc & 1) * STAGE_BYTES;
            const uint32_t sA_lo = sA_hi + TILE_B * 2;
            const uint32_t sB_hi = sA_hi + 2 * TILE_B * 2;
            const uint32_t sB_lo = sA_hi + 3 * TILE_B * 2;

            #pragma unroll
            for (int kss = 0; kss < 2; kss++) {
                const int ks = kss ^ ks_xor;            // de-phased
                const int k0 = ks * 16;
                uint32_t aH[2][4], aL[2][4];
                const int afr = lane & 15;
                const int afc = k0 + (lane >> 4) * 8;
                #pragma unroll
                for (int mi = 0; mi < 2; mi++) {
                    uint32_t ad = (uint32_t)((wm + mi * 16 + afr) * LDA + afc) * 2;
                    ldsm_x4(aH[mi], sA_hi + ad);
                    ldsm_x4(aL[mi], sA_lo + ad);
                }
                #pragma unroll
                for (int gg = 0; gg < 2; gg++) {
                    const int g = gg ^ g_xor;           // de-phased
                    uint32_t bH[4][2], bL[4][2];
                    #pragma unroll
                    for (int nq = 0; nq < 4; nq++) {
                        const int nb = g * 4 + nq;
                        const int brow = wn + nb * 8 + (lane & 7);
                        const int bcol = k0 + ((lane >> 3) & 1) * 8;
                        uint32_t bd = (uint32_t)(brow * LDA + bcol) * 2;
                        ldsm_x2(bH[nq], sB_hi + bd);
                        ldsm_x2(bL[nq], sB_lo + bd);
                    }
                    #pragma unroll
                    for (int nq = 0; nq < 4; nq++)
                        #pragma unroll
                        for (int mi = 0; mi < 2; mi++)
                            mma_bf16(acc[mi][g * 4 + nq], aH[mi], bH[nq]);
                    #pragma unroll
                    for (int nq = 0; nq < 4; nq++)
                        #pragma unroll
                        for (int mi = 0; mi < 2; mi++)
                            mma_bf16(acc[mi][g * 4 + nq], aL[mi], bH[nq]);
                    #pragma unroll
                    for (int nq = 0; nq < 4; nq++)
                        #pragma unroll
                        for (int mi = 0; mi < 2; mi++)
                            mma_bf16(acc[mi][g * 4 + nq], aH[mi], bL[nq]);
                }
            }
        }
        __syncthreads();

        const int kn = kc + 2;
        if (kn < 32)
            issue_chunk(sm_addr + (uint32_t)(kc & 1) * STAGE_BYTES, mrow0, n0, kn, arow, acol);
        CP_COMMIT();
    }

    // ---- epilogue: bias + write h (fp16) + fused BN stats (fp32) ----
    const int l4 = lane >> 2;
    const int lc = (lane & 3) * 2;

    #pragma unroll
    for (int mi = 0; mi < 2; mi++) {
        #pragma unroll
        for (int rr = 0; rr < 2; rr++) {
            const int row = wm + mi * 16 + rr * 8 + l4;
            const size_t grow = (size_t)mrow0 + row;
            const float rsv = g_rs[grow];
            __half* hrow = g_h + grow * CDIM + n0;
            float lsum = 0.f, lsq = 0.f;
            #pragma unroll
            for (int nb = 0; nb < 8; nb++) {
                const int c = wn + nb * 8 + lc;
                float v0 = acc[mi][nb][rr * 2 + 0] + rsv * sBias[c]     + sBias[128 + c];
                float v1 = acc[mi][nb][rr * 2 + 1] + rsv * sBias[c + 1] + sBias[128 + c + 1];
                lsum += v0 + v1;
                lsq  += v0 * v0 + v1 * v1;
                *reinterpret_cast<__half2*>(hrow + c) = __floats2half2_rn(v0, v1);
            }
            lsum += __shfl_xor_sync(0xFFFFFFFF, lsum, 1);
            lsq  += __shfl_xor_sync(0xFFFFFFFF, lsq, 1);
            lsum += __shfl_xor_sync(0xFFFFFFFF, lsum, 2);
            lsq  += __shfl_xor_sync(0xFFFFFFFF, lsq, 2);
            if ((lane & 3) == 0) {
                int node = (int)(grow % NNODE);
                atomicAdd(&sred[node], lsum);
                atomicAdd(&sred[12 + node], lsq);
            }
        }
    }
    __syncthreads();
    if (tid < NNODE) {
        atomicAdd(&g_sum[tid], sred[tid]);
        atomicAdd(&g_sumsq[tid], sred[12 + tid]);
    }
}

// ============================================================================
// Kernel 3: finalize BN stats
// ============================================================================
__global__ void k_finalize(const float* __restrict__ gamma, const float* __restrict__ beta) {
    int t = threadIdx.x;
    if (t < NNODE) {
        const float inv_n = 1.0f / ((float)NB * (float)CDIM);
        float mean = g_sum[t] * inv_n;
        float var  = g_sumsq[t] * inv_n - mean * mean;
        var = fmaxf(var, 0.f);
        float sc = gamma[t] * rsqrtf(var + BN_EPS);
        g_scale[t] = sc;
        g_shift[t] = beta[t] - mean * sc;
    }
}

// ============================================================================
// Kernel 4: out = relu(x + h*scale + shift)   (8 elems/thread, h fp16)
// ============================================================================
__global__ __launch_bounds__(512) void k_output(const float* __restrict__ x,
                                                float* __restrict__ out) {
    const size_t g8 = (size_t)blockIdx.x * 512 + threadIdx.x;  // unit of 8 floats
    const uint4 hraw = reinterpret_cast<const uint4*>(g_h)[g8];
    const float4 xv0 = reinterpret_cast<const float4*>(x)[g8 * 2];
    const float4 xv1 = reinterpret_cast<const float4*>(x)[g8 * 2 + 1];
    const int node = (int)((g8 >> 6) % NNODE);                  // 64 groups/row
    const float sc = g_scale[node], sh = g_shift[node];

    float2 h0 = __half22float2(*reinterpret_cast<const __half2*>(&hraw.x));
    float2 h1 = __half22float2(*reinterpret_cast<const __half2*>(&hraw.y));
    float2 h2 = __half22float2(*reinterpret_cast<const __half2*>(&hraw.z));
    float2 h3 = __half22float2(*reinterpret_cast<const __half2*>(&hraw.w));

    float4 o0, o1;
    o0.x = fmaxf(fmaf(h0.x, sc, sh) + xv0.x, 0.f);
    o0.y = fmaxf(fmaf(h0.y, sc, sh) + xv0.y, 0.f);
    o0.z = fmaxf(fmaf(h1.x, sc, sh) + xv0.z, 0.f);
    o0.w = fmaxf(fmaf(h1.y, sc, sh) + xv0.w, 0.f);
    o1.x = fmaxf(fmaf(h2.x, sc, sh) + xv1.x, 0.f);
    o1.y = fmaxf(fmaf(h2.y, sc, sh) + xv1.y, 0.f);
    o1.z = fmaxf(fmaf(h3.x, sc, sh) + xv1.z, 0.f);
    o1.w = fmaxf(fmaf(h3.y, sc, sh) + xv1.w, 0.f);
    reinterpret_cast<float4*>(out)[g8 * 2]     = o0;
    reinterpret_cast<float4*>(out)[g8 * 2 + 1] = o1;
}

// ============================================================================
// Launch
// ============================================================================
extern "C" void kernel_launch(void* const* d_in, const int* in_sizes, int n_in,
                              void* d_out, int out_size) {
    const float* x     = (const float*)d_in[0];
    const float* Uw    = (const float*)d_in[1];
    const float* Ub    = (const float*)d_in[2];
    const float* Vw    = (const float*)d_in[3];
    const float* Vb    = (const float*)d_in[4];
    const float* gamma = (const float*)d_in[5];
    const float* beta  = (const float*)d_in[6];
    float* out = (float*)d_out;

    cudaFuncSetAttribute(k_gemm, cudaFuncAttributeMaxDynamicSharedMemorySize, SMEM2_BYTES);

    k_zero_stats<<<1, 32>>>();
    k_prep_w<<<(NDIM * KDIM + 255) / 256, 256>>>(Uw, Vw);
    k_adjacency<<<NB, 128>>>(x);
    k_gemm<<<(ROWS / 128) * 4, 256, SMEM2_BYTES>>>(Vb, Ub);
    k_finalize<<<1, 32>>>(gamma, beta);
    k_output<<<(unsigned)((size_t)ROWS * CDIM / 8 / 512), 512>>>(x, out);
}

// round 12
// speedup vs baseline: 2.1497x; 2.1497x over previous
#include <cuda_runtime.h>
#include <cuda_bf16.h>
#include <cuda_fp16.h>
#include <cstdint>

// ============================================================================
// Problem constants
// ============================================================================
#define NB     16384
#define NNODE  12
#define CDIM   512
#define SXLD   (CDIM + 4)      // padded smem row (bank-conflict fix)
#define ROWS   (NB * NNODE)
#define KDIM   1024
#define NDIM   512
#define TOPK   4
#define BN_EPS 1e-5f

// ============================================================================
// Helpers (baseline PTX only)
// ============================================================================
__device__ __forceinline__ uint32_t smem_u32(const void* p) {
    uint32_t a;
    asm("{ .reg .u64 t; cvta.to.shared.u64 t, %1; cvt.u32.u64 %0, t; }" : "=r"(a) : "l"(p));
    return a;
}
__device__ __forceinline__ void ldsm_x4(uint32_t* r, uint32_t addr) {
    asm volatile("ldmatrix.sync.aligned.m8n8.x4.shared.b16 {%0,%1,%2,%3}, [%4];"
                 : "=r"(r[0]), "=r"(r[1]), "=r"(r[2]), "=r"(r[3]) : "r"(addr));
}
__device__ __forceinline__ void ldsm_x2(uint32_t* r, uint32_t addr) {
    asm volatile("ldmatrix.sync.aligned.m8n8.x2.shared.b16 {%0,%1}, [%2];"
                 : "=r"(r[0]), "=r"(r[1]) : "r"(addr));
}
__device__ __forceinline__ void cp_async16(uint32_t saddr, const void* gaddr) {
    asm volatile("cp.async.cg.shared.global [%0], [%1], 16;" :: "r"(saddr), "l"(gaddr));
}
#define CP_COMMIT() asm volatile("cp.async.commit_group;" ::: "memory")
#define CP_WAIT1()  asm volatile("cp.async.wait_group 1;" ::: "memory")

__device__ __forceinline__ void mma_bf16(float* d, const uint32_t* a, const uint32_t* b) {
    asm volatile(
        "mma.sync.aligned.m16n8k16.row.col.f32.bf16.bf16.f32 "
        "{%0,%1,%2,%3}, {%4,%5,%6,%7}, {%8,%9}, {%0,%1,%2,%3};"
        : "+f"(d[0]), "+f"(d[1]), "+f"(d[2]), "+f"(d[3])
        : "r"(a[0]), "r"(a[1]), "r"(a[2]), "r"(a[3]), "r"(b[0]), "r"(b[1]));
}
__device__ __forceinline__ uint32_t pack_hi2(float a, float b) {
    __nv_bfloat162 t;
    t.x = __float2bfloat16(a);
    t.y = __float2bfloat16(b);
    return *reinterpret_cast<uint32_t*>(&t);
}
__device__ __forceinline__ uint32_t pack_lo2(float a, float b) {
    __nv_bfloat162 t;
    __nv_bfloat16 ha = __float2bfloat16(a);
    __nv_bfloat16 hb = __float2bfloat16(b);
    t.x = __float2bfloat16(a - __bfloat162float(ha));
    t.y = __float2bfloat16(b - __bfloat162float(hb));
    return *reinterpret_cast<uint32_t*>(&t);
}

// ============================================================================
// Device scratch  (h stored as fp16)
// ============================================================================
__device__ __align__(16) __nv_bfloat16 g_ahi[(size_t)ROWS * KDIM];
__device__ __align__(16) __nv_bfloat16 g_alo[(size_t)ROWS * KDIM];
__device__ __align__(16) __nv_bfloat16 g_whi[(size_t)NDIM * KDIM];
__device__ __align__(16) __nv_bfloat16 g_wlo[(size_t)NDIM * KDIM];
__device__ __align__(16) __half g_h[(size_t)ROWS * CDIM];
__device__ float g_rs[ROWS];
__device__ float g_sum[NNODE];
__device__ float g_sumsq[NNODE];
__device__ float g_scale[NNODE];
__device__ float g_shift[NNODE];

// ============================================================================
// Kernel 0a
// ============================================================================
__global__ void k_zero_stats() {
    int t = threadIdx.x;
    if (t < NNODE) { g_sum[t] = 0.f; g_sumsq[t] = 0.f; }
}

// ============================================================================
// Kernel 0b: pack W = [Vw | Uw] as bf16 hi/lo
// ============================================================================
__global__ void k_prep_w(const float* __restrict__ Uw, const float* __restrict__ Vw) {
    int idx = blockIdx.x * blockDim.x + threadIdx.x;
    if (idx >= NDIM * KDIM) return;
    int d = idx >> 10;
    int k = idx & 1023;
    float v = (k < 512) ? Vw[d * 512 + k] : Uw[d * 512 + (k - 512)];
    __nv_bfloat16 hi = __float2bfloat16(v);
    float lo = v - __bfloat162float(hi);
    g_whi[idx] = hi;
    g_wlo[idx] = __float2bfloat16(lo);
}

// ============================================================================
// Kernel 1: adjacency + aggregation -> A-operand rows [y | x] (hi/lo)
// ============================================================================
__global__ __launch_bounds__(128) void k_adjacency(const float* __restrict__ x) {
    __shared__ __align__(16) float sx[NNODE][SXLD];
    __shared__ float ssim[NNODE][NNODE];
    __shared__ float sA[NNODE][NNODE];
    __shared__ float sthr[NNODE];
    __shared__ float sdinv[NNODE];

    const int tid = threadIdx.x;
    const int b   = blockIdx.x;

    {
        const float4* src = reinterpret_cast<const float4*>(x + (size_t)b * NNODE * CDIM);
        for (int u = tid; u < NNODE * CDIM / 4; u += 128) {
            int i = u >> 7;
            int q = u & 127;
            *reinterpret_cast<float4*>(&sx[i][q * 4]) = src[u];
        }
    }
    __syncthreads();

    if (tid < 78) {
        int i = 0, t = tid;
        while (t >= NNODE - i) { t -= NNODE - i; i++; }
        int j = i + t;
        float a0 = 0.f, a1 = 0.f, a2 = 0.f, a3 = 0.f;
        #pragma unroll 4
        for (int c = 0; c < CDIM; c += 4) {
            float4 a  = *reinterpret_cast<const float4*>(&sx[i][c]);
            float4 bb = *reinterpret_cast<const float4*>(&sx[j][c]);
            a0 += a.x * bb.x; a1 += a.y * bb.y;
            a2 += a.z * bb.z; a3 += a.w * bb.w;
        }
        float acc = (a0 + a1) + (a2 + a3);
        ssim[i][j] = acc;
        ssim[j][i] = acc;
    }
    __syncthreads();

    if (tid < NNODE) {
        float v[NNODE];
        #pragma unroll
        for (int j = 0; j < NNODE; j++) v[j] = ssim[tid][j];
        float thr = 0.f;
        #pragma unroll
        for (int t = 0; t < TOPK; t++) {
            int m = 0;
            float mv = v[0];
            #pragma unroll
            for (int j = 1; j < NNODE; j++) if (v[j] > mv) { mv = v[j]; m = j; }
            thr = mv;
            v[m] = -3.4e38f;
        }
        sthr[tid] = thr;
        int deg = 0;
        #pragma unroll
        for (int j = 0; j < NNODE; j++) deg += (ssim[tid][j] >= thr) ? 1 : 0;
        sdinv[tid] = rsqrtf((float)deg);
    }
    __syncthreads();

    for (int t = tid; t < NNODE * NNODE; t += 128) {
        int i = t / NNODE, j = t % NNODE;
        float adj = (ssim[i][j] >= sthr[i]) ? 1.f : 0.f;
        sA[i][j] = sdinv[i] * sdinv[j] * adj;
    }
    __syncthreads();

    if (tid < NNODE) {
        float rs = 0.f;
        #pragma unroll
        for (int j = 0; j < NNODE; j++) rs += sA[tid][j];
        g_rs[(size_t)b * NNODE + tid] = rs;
    }

    // y = A @ x -> cols [0,512)
    {
        const int c0 = tid * 4;
        float4 xv[NNODE];
        #pragma unroll
        for (int j = 0; j < NNODE; j++)
            xv[j] = *reinterpret_cast<const float4*>(&sx[j][c0]);
        #pragma unroll
        for (int i = 0; i < NNODE; i++) {
            float a0 = 0.f, a1 = 0.f, a2 = 0.f, a3 = 0.f;
            #pragma unroll
            for (int j = 0; j < NNODE; j++) {
                float w = sA[i][j];
                a0 += w * xv[j].x; a1 += w * xv[j].y;
                a2 += w * xv[j].z; a3 += w * xv[j].w;
            }
            size_t o = ((size_t)b * NNODE + i) * KDIM + c0;
            uint2 hi = make_uint2(pack_hi2(a0, a1), pack_hi2(a2, a3));
            uint2 lo = make_uint2(pack_lo2(a0, a1), pack_lo2(a2, a3));
            *reinterpret_cast<uint2*>(g_ahi + o) = hi;
            *reinterpret_cast<uint2*>(g_alo + o) = lo;
        }
    }

    // x -> cols [512,1024)
    for (int u = tid; u < NNODE * 128; u += 128) {
        int i = u >> 7, q = u & 127;
        float4 v = *reinterpret_cast<const float4*>(&sx[i][q * 4]);
        size_t o = ((size_t)b * NNODE + i) * KDIM + 512 + q * 4;
        uint2 hi = make_uint2(pack_hi2(v.x, v.y), pack_hi2(v.z, v.w));
        uint2 lo = make_uint2(pack_lo2(v.x, v.y), pack_lo2(v.z, v.w));
        *reinterpret_cast<uint2*>(g_ahi + o) = hi;
        *reinterpret_cast<uint2*>(g_alo + o) = lo;
    }
}

// ============================================================================
// Kernel 2: GEMM  h = [y|x] @ Wcat^T + rs*Vb + Ub   (bf16x3, HMMA, ldmatrix)
// R10 structure + COMPILE-TIME warp de-phasing (templated mainloop so all
// accumulator indices stay constant -> no local-memory spill).
// ============================================================================
#define LDA        40
#define TILE_B     (128 * LDA)
#define STAGE_E    (4 * TILE_B)
#define STAGE_BYTES (STAGE_E * 2)          // 40960
#define SMEM2_BYTES (2 * STAGE_BYTES)      // 81920

__device__ __forceinline__ void issue_chunk(uint32_t sbase, int mrow0, int n0,
                                            int kc, int arow, int acol) {
    const size_t ga = (size_t)(mrow0 + arow) * KDIM + kc * 32 + acol;
    const size_t gw = (size_t)(n0 + arow) * KDIM + kc * 32 + acol;
    const uint32_t off = (uint32_t)(arow * LDA + acol) * 2;
    cp_async16(sbase + off,                     g_ahi + ga);
    cp_async16(sbase + off + 16,                g_ahi + ga + 8);
    cp_async16(sbase + TILE_B * 2 + off,        g_alo + ga);
    cp_async16(sbase + TILE_B * 2 + off + 16,   g_alo + ga + 8);
    cp_async16(sbase + 2 * TILE_B * 2 + off,      g_whi + gw);
    cp_async16(sbase + 2 * TILE_B * 2 + off + 16, g_whi + gw + 8);
    cp_async16(sbase + 3 * TILE_B * 2 + off,      g_wlo + gw);
    cp_async16(sbase + 3 * TILE_B * 2 + off + 16, g_wlo + gw + 8);
}

template<int KSX, int GX>
__device__ __forceinline__ void gemm_mainloop(
    uint32_t sm_addr, int mrow0, int n0, int arow, int acol,
    int wm, int wn, int lane, float (&acc)[2][8][4])
{
    issue_chunk(sm_addr, mrow0, n0, 0, arow, acol);
    CP_COMMIT();
    issue_chunk(sm_addr + STAGE_BYTES, mrow0, n0, 1, arow, acol);
    CP_COMMIT();

    #pragma unroll 1
    for (int kc = 0; kc < 32; kc++) {
        CP_WAIT1();
        __syncthreads();

        {
            const uint32_t sA_hi = sm_addr + (uint32_t)(kc & 1) * STAGE_BYTES;
            const uint32_t sA_lo = sA_hi + TILE_B * 2;
            const uint32_t sB_hi = sA_hi + 2 * TILE_B * 2;
            const uint32_t sB_lo = sA_hi + 3 * TILE_B * 2;

            #pragma unroll
            for (int kss = 0; kss < 2; kss++) {
                const int ks = kss ^ KSX;              // compile-time after unroll
                const int k0 = ks * 16;
                uint32_t aH[2][4], aL[2][4];
                const int afr = lane & 15;
                const int afc = k0 + (lane >> 4) * 8;
                #pragma unroll
                for (int mi = 0; mi < 2; mi++) {
                    uint32_t ad = (uint32_t)((wm + mi * 16 + afr) * LDA + afc) * 2;
                    ldsm_x4(aH[mi], sA_hi + ad);
                    ldsm_x4(aL[mi], sA_lo + ad);
                }
                #pragma unroll
                for (int gg = 0; gg < 2; gg++) {
                    const int g = gg ^ GX;             // compile-time after unroll
                    uint32_t bH[4][2], bL[4][2];
                    #pragma unroll
                    for (int nq = 0; nq < 4; nq++) {
                        const int nb = g * 4 + nq;
                        const int brow = wn + nb * 8 + (lane & 7);
                        const int bcol = k0 + ((lane >> 3) & 1) * 8;
                        uint32_t bd = (uint32_t)(brow * LDA + bcol) * 2;
                        ldsm_x2(bH[nq], sB_hi + bd);
                        ldsm_x2(bL[nq], sB_lo + bd);
                    }
                    #pragma unroll
                    for (int nq = 0; nq < 4; nq++)
                        #pragma unroll
                        for (int mi = 0; mi < 2; mi++)
                            mma_bf16(acc[mi][g * 4 + nq], aH[mi], bH[nq]);
                    #pragma unroll
                    for (int nq = 0; nq < 4; nq++)
                        #pragma unroll
                        for (int mi = 0; mi < 2; mi++)
                            mma_bf16(acc[mi][g * 4 + nq], aL[mi], bH[nq]);
                    #pragma unroll
                    for (int nq = 0; nq < 4; nq++)
                        #pragma unroll
                        for (int mi = 0; mi < 2; mi++)
                            mma_bf16(acc[mi][g * 4 + nq], aH[mi], bL[nq]);
                }
            }
        }
        __syncthreads();

        const int kn = kc + 2;
        if (kn < 32)
            issue_chunk(sm_addr + (uint32_t)(kc & 1) * STAGE_BYTES, mrow0, n0, kn, arow, acol);
        CP_COMMIT();
    }
}

__global__ __launch_bounds__(256, 2) void k_gemm(const float* __restrict__ Vb,
                                                 const float* __restrict__ Ub) {
    extern __shared__ __align__(128) __nv_bfloat16 sm[];
    __shared__ float sBias[256];
    __shared__ float sred[24];

    const int tid  = threadIdx.x;
    const int wid  = tid >> 5;
    const int lane = tid & 31;

    const int ntile = blockIdx.x & 3;
    const int mtile = blockIdx.x >> 2;
    const int mrow0 = mtile * 128;
    const int n0    = ntile * 128;

    const int wm = (wid & 3) * 32;
    const int wn = (wid >> 2) * 64;

    for (int i = tid; i < 128; i += 256) {
        sBias[i]       = Vb[n0 + i];
        sBias[128 + i] = Ub[n0 + i];
    }
    if (tid < 24) sred[tid] = 0.f;

    float acc[2][8][4];
    #pragma unroll
    for (int mi = 0; mi < 2; mi++)
        #pragma unroll
        for (int nb = 0; nb < 8; nb++)
            #pragma unroll
            for (int q = 0; q < 4; q++) acc[mi][nb][q] = 0.f;

    const int arow = tid >> 1;
    const int acol = (tid & 1) * 16;
    const uint32_t sm_addr = smem_u32(sm);

    // Warp-uniform dispatch to compile-time de-phased mainloops.
    // 4 phase groups; each instance has identical barrier counts (legal).
    const int ks_xor = (wid >> 1) & 1;
    const int g_xor  = wid & 1;
    if (ks_xor == 0) {
        if (g_xor == 0) gemm_mainloop<0,0>(sm_addr, mrow0, n0, arow, acol, wm, wn, lane, acc);
        else            gemm_mainloop<0,1>(sm_addr, mrow0, n0, arow, acol, wm, wn, lane, acc);
    } else {
        if (g_xor == 0) gemm_mainloop<1,0>(sm_addr, mrow0, n0, arow, acol, wm, wn, lane, acc);
        else            gemm_mainloop<1,1>(sm_addr, mrow0, n0, arow, acol, wm, wn, lane, acc);
    }

    // ---- epilogue: bias + write h (fp16) + fused BN stats (fp32) ----
    const int l4 = lane >> 2;
    const int lc = (lane & 3) * 2;

    #pragma unroll
    for (int mi = 0; mi < 2; mi++) {
        #pragma unroll
        for (int rr = 0; rr < 2; rr++) {
            const int row = wm + mi * 16 + rr * 8 + l4;
            const size_t grow = (size_t)mrow0 + row;
            const float rsv = g_rs[grow];
            __half* hrow = g_h + grow * CDIM + n0;
            float lsum = 0.f, lsq = 0.f;
            #pragma unroll
            for (int nb = 0; nb < 8; nb++) {
                const int c = wn + nb * 8 + lc;
                float v0 = acc[mi][nb][rr * 2 + 0] + rsv * sBias[c]     + sBias[128 + c];
                float v1 = acc[mi][nb][rr * 2 + 1] + rsv * sBias[c + 1] + sBias[128 + c + 1];
                lsum += v0 + v1;
                lsq  += v0 * v0 + v1 * v1;
                *reinterpret_cast<__half2*>(hrow + c) = __floats2half2_rn(v0, v1);
            }
            lsum += __shfl_xor_sync(0xFFFFFFFF, lsum, 1);
            lsq  += __shfl_xor_sync(0xFFFFFFFF, lsq, 1);
            lsum += __shfl_xor_sync(0xFFFFFFFF, lsum, 2);
            lsq  += __shfl_xor_sync(0xFFFFFFFF, lsq, 2);
            if ((lane & 3) == 0) {
                int node = (int)(grow % NNODE);
                atomicAdd(&sred[node], lsum);
                atomicAdd(&sred[12 + node], lsq);
            }
        }
    }
    __syncthreads();
    if (tid < NNODE) {
        atomicAdd(&g_sum[tid], sred[tid]);
        atomicAdd(&g_sumsq[tid], sred[12 + tid]);
    }
}

// ============================================================================
// Kernel 3: finalize BN stats
// ============================================================================
__global__ void k_finalize(const float* __restrict__ gamma, const float* __restrict__ beta) {
    int t = threadIdx.x;
    if (t < NNODE) {
        const float inv_n = 1.0f / ((float)NB * (float)CDIM);
        float mean = g_sum[t] * inv_n;
        float var  = g_sumsq[t] * inv_n - mean * mean;
        var = fmaxf(var, 0.f);
        float sc = gamma[t] * rsqrtf(var + BN_EPS);
        g_scale[t] = sc;
        g_shift[t] = beta[t] - mean * sc;
    }
}

// ============================================================================
// Kernel 4: out = relu(x + h*scale + shift)   (8 elems/thread, h fp16)
// ============================================================================
__global__ __launch_bounds__(512) void k_output(const float* __restrict__ x,
                                                float* __restrict__ out) {
    const size_t g8 = (size_t)blockIdx.x * 512 + threadIdx.x;
    const uint4 hraw = reinterpret_cast<const uint4*>(g_h)[g8];
    const float4 xv0 = reinterpret_cast<const float4*>(x)[g8 * 2];
    const float4 xv1 = reinterpret_cast<const float4*>(x)[g8 * 2 + 1];
    const int node = (int)((g8 >> 6) % NNODE);
    const float sc = g_scale[node], sh = g_shift[node];

    float2 h0 = __half22float2(*reinterpret_cast<const __half2*>(&hraw.x));
    float2 h1 = __half22float2(*reinterpret_cast<const __half2*>(&hraw.y));
    float2 h2 = __half22float2(*reinterpret_cast<const __half2*>(&hraw.z));
    float2 h3 = __half22float2(*reinterpret_cast<const __half2*>(&hraw.w));

    float4 o0, o1;
    o0.x = fmaxf(fmaf(h0.x, sc, sh) + xv0.x, 0.f);
    o0.y = fmaxf(fmaf(h0.y, sc, sh) + xv0.y, 0.f);
    o0.z = fmaxf(fmaf(h1.x, sc, sh) + xv0.z, 0.f);
    o0.w = fmaxf(fmaf(h1.y, sc, sh) + xv0.w, 0.f);
    o1.x = fmaxf(fmaf(h2.x, sc, sh) + xv1.x, 0.f);
    o1.y = fmaxf(fmaf(h2.y, sc, sh) + xv1.y, 0.f);
    o1.z = fmaxf(fmaf(h3.x, sc, sh) + xv1.z, 0.f);
    o1.w = fmaxf(fmaf(h3.y, sc, sh) + xv1.w, 0.f);
    reinterpret_cast<float4*>(out)[g8 * 2]     = o0;
    reinterpret_cast<float4*>(out)[g8 * 2 + 1] = o1;
}

// ============================================================================
// Launch
// ============================================================================
extern "C" void kernel_launch(void* const* d_in, const int* in_sizes, int n_in,
                              void* d_out, int out_size) {
    const float* x     = (const float*)d_in[0];
    const float* Uw    = (const float*)d_in[1];
    const float* Ub    = (const float*)d_in[2];
    const float* Vw    = (const float*)d_in[3];
    const float* Vb    = (const float*)d_in[4];
    const float* gamma = (const float*)d_in[5];
    const float* beta  = (const float*)d_in[6];
    float* out = (float*)d_out;

    cudaFuncSetAttribute(k_gemm, cudaFuncAttributeMaxDynamicSharedMemorySize, SMEM2_BYTES);

    k_zero_stats<<<1, 32>>>();
    k_prep_w<<<(NDIM * KDIM + 255) / 256, 256>>>(Uw, Vw);
    k_adjacency<<<NB, 128>>>(x);
    k_gemm<<<(ROWS / 128) * 4, 256, SMEM2_BYTES>>>(Vb, Ub);
    k_finalize<<<1, 32>>>(gamma, beta);
    k_output<<<(unsigned)((size_t)ROWS * CDIM / 8 / 512), 512>>>(x, out);
}

// round 13
// speedup vs baseline: 3.9435x; 1.8345x over previous
#include <cuda_runtime.h>
#include <cuda_bf16.h>
#include <cuda_fp16.h>
#include <cstdint>

// ============================================================================
// Problem constants
// ============================================================================
#define NB     16384
#define NNODE  12
#define CDIM   512
#define SXLD   (CDIM + 4)      // padded smem row (bank-conflict fix)
#define ROWS   (NB * NNODE)
#define KDIM   1024
#define NDIM   512
#define TOPK   4
#define BN_EPS 1e-5f

// ============================================================================
// Helpers (baseline PTX only)
// ============================================================================
__device__ __forceinline__ uint32_t smem_u32(const void* p) {
    uint32_t a;
    asm("{ .reg .u64 t; cvta.to.shared.u64 t, %1; cvt.u32.u64 %0, t; }" : "=r"(a) : "l"(p));
    return a;
}
__device__ __forceinline__ void ldsm_x4(uint32_t* r, uint32_t addr) {
    asm volatile("ldmatrix.sync.aligned.m8n8.x4.shared.b16 {%0,%1,%2,%3}, [%4];"
                 : "=r"(r[0]), "=r"(r[1]), "=r"(r[2]), "=r"(r[3]) : "r"(addr));
}
__device__ __forceinline__ void ldsm_x2(uint32_t* r, uint32_t addr) {
    asm volatile("ldmatrix.sync.aligned.m8n8.x2.shared.b16 {%0,%1}, [%2];"
                 : "=r"(r[0]), "=r"(r[1]) : "r"(addr));
}
__device__ __forceinline__ void cp_async16(uint32_t saddr, const void* gaddr) {
    asm volatile("cp.async.cg.shared.global [%0], [%1], 16;" :: "r"(saddr), "l"(gaddr));
}
#define CP_COMMIT() asm volatile("cp.async.commit_group;" ::: "memory")
#define CP_WAIT1()  asm volatile("cp.async.wait_group 1;" ::: "memory")

// D += A * B^T : m16n8k16 row.col fp16 -> f32  (single-term, 11-bit mantissa)
__device__ __forceinline__ void mma_f16(float* d, const uint32_t* a, const uint32_t* b) {
    asm volatile(
        "mma.sync.aligned.m16n8k16.row.col.f32.f16.f16.f32 "
        "{%0,%1,%2,%3}, {%4,%5,%6,%7}, {%8,%9}, {%0,%1,%2,%3};"
        : "+f"(d[0]), "+f"(d[1]), "+f"(d[2]), "+f"(d[3])
        : "r"(a[0]), "r"(a[1]), "r"(a[2]), "r"(a[3]), "r"(b[0]), "r"(b[1]));
}

// ============================================================================
// Device scratch  (A operand + W + h all fp16)
// ============================================================================
__device__ __align__(16) __half g_a[(size_t)ROWS * KDIM];   // [y | x] fp16
__device__ __align__(16) __half g_w[(size_t)NDIM * KDIM];   // [Vw | Uw] fp16
__device__ __align__(16) __half g_h[(size_t)ROWS * CDIM];
__device__ float g_rs[ROWS];
__device__ float g_sum[NNODE];
__device__ float g_sumsq[NNODE];
__device__ float g_scale[NNODE];
__device__ float g_shift[NNODE];

// ============================================================================
// Kernel 0a
// ============================================================================
__global__ void k_zero_stats() {
    int t = threadIdx.x;
    if (t < NNODE) { g_sum[t] = 0.f; g_sumsq[t] = 0.f; }
}

// ============================================================================
// Kernel 0b: pack W = [Vw | Uw] as fp16
// ============================================================================
__global__ void k_prep_w(const float* __restrict__ Uw, const float* __restrict__ Vw) {
    int idx = blockIdx.x * blockDim.x + threadIdx.x;
    if (idx >= NDIM * KDIM) return;
    int d = idx >> 10;
    int k = idx & 1023;
    float v = (k < 512) ? Vw[d * 512 + k] : Uw[d * 512 + (k - 512)];
    g_w[idx] = __float2half_rn(v);
}

// ============================================================================
// Kernel 1: adjacency + aggregation -> A-operand rows [y | x] (fp16)
// ============================================================================
__global__ __launch_bounds__(128) void k_adjacency(const float* __restrict__ x) {
    __shared__ __align__(16) float sx[NNODE][SXLD];
    __shared__ float ssim[NNODE][NNODE];
    __shared__ float sA[NNODE][NNODE];
    __shared__ float sthr[NNODE];
    __shared__ float sdinv[NNODE];

    const int tid = threadIdx.x;
    const int b   = blockIdx.x;

    {
        const float4* src = reinterpret_cast<const float4*>(x + (size_t)b * NNODE * CDIM);
        for (int u = tid; u < NNODE * CDIM / 4; u += 128) {
            int i = u >> 7;
            int q = u & 127;
            *reinterpret_cast<float4*>(&sx[i][q * 4]) = src[u];
        }
    }
    __syncthreads();

    if (tid < 78) {
        int i = 0, t = tid;
        while (t >= NNODE - i) { t -= NNODE - i; i++; }
        int j = i + t;
        float a0 = 0.f, a1 = 0.f, a2 = 0.f, a3 = 0.f;
        #pragma unroll 4
        for (int c = 0; c < CDIM; c += 4) {
            float4 a  = *reinterpret_cast<const float4*>(&sx[i][c]);
            float4 bb = *reinterpret_cast<const float4*>(&sx[j][c]);
            a0 += a.x * bb.x; a1 += a.y * bb.y;
            a2 += a.z * bb.z; a3 += a.w * bb.w;
        }
        float acc = (a0 + a1) + (a2 + a3);
        ssim[i][j] = acc;
        ssim[j][i] = acc;
    }
    __syncthreads();

    if (tid < NNODE) {
        float v[NNODE];
        #pragma unroll
        for (int j = 0; j < NNODE; j++) v[j] = ssim[tid][j];
        float thr = 0.f;
        #pragma unroll
        for (int t = 0; t < TOPK; t++) {
            int m = 0;
            float mv = v[0];
            #pragma unroll
            for (int j = 1; j < NNODE; j++) if (v[j] > mv) { mv = v[j]; m = j; }
            thr = mv;
            v[m] = -3.4e38f;
        }
        sthr[tid] = thr;
        int deg = 0;
        #pragma unroll
        for (int j = 0; j < NNODE; j++) deg += (ssim[tid][j] >= thr) ? 1 : 0;
        sdinv[tid] = rsqrtf((float)deg);
    }
    __syncthreads();

    for (int t = tid; t < NNODE * NNODE; t += 128) {
        int i = t / NNODE, j = t % NNODE;
        float adj = (ssim[i][j] >= sthr[i]) ? 1.f : 0.f;
        sA[i][j] = sdinv[i] * sdinv[j] * adj;
    }
    __syncthreads();

    if (tid < NNODE) {
        float rs = 0.f;
        #pragma unroll
        for (int j = 0; j < NNODE; j++) rs += sA[tid][j];
        g_rs[(size_t)b * NNODE + tid] = rs;
    }

    // y = A @ x -> cols [0,512) fp16
    {
        const int c0 = tid * 4;
        float4 xv[NNODE];
        #pragma unroll
        for (int j = 0; j < NNODE; j++)
            xv[j] = *reinterpret_cast<const float4*>(&sx[j][c0]);
        #pragma unroll
        for (int i = 0; i < NNODE; i++) {
            float a0 = 0.f, a1 = 0.f, a2 = 0.f, a3 = 0.f;
            #pragma unroll
            for (int j = 0; j < NNODE; j++) {
                float w = sA[i][j];
                a0 += w * xv[j].x; a1 += w * xv[j].y;
                a2 += w * xv[j].z; a3 += w * xv[j].w;
            }
            size_t o = ((size_t)b * NNODE + i) * KDIM + c0;
            __half2 p0 = __floats2half2_rn(a0, a1);
            __half2 p1 = __floats2half2_rn(a2, a3);
            *reinterpret_cast<__half2*>(g_a + o)     = p0;
            *reinterpret_cast<__half2*>(g_a + o + 2) = p1;
        }
    }

    // x -> cols [512,1024) fp16
    for (int u = tid; u < NNODE * 128; u += 128) {
        int i = u >> 7, q = u & 127;
        float4 v = *reinterpret_cast<const float4*>(&sx[i][q * 4]);
        size_t o = ((size_t)b * NNODE + i) * KDIM + 512 + q * 4;
        __half2 p0 = __floats2half2_rn(v.x, v.y);
        __half2 p1 = __floats2half2_rn(v.z, v.w);
        *reinterpret_cast<__half2*>(g_a + o)     = p0;
        *reinterpret_cast<__half2*>(g_a + o + 2) = p1;
    }
}

// ============================================================================
// Kernel 2: GEMM  h = [y|x] @ Wcat^T + rs*Vb + Ub   (fp16 single-term HMMA)
// BM=128, BN=128, BK=32, 256 thr, 2-stage cp.async (WAIT1, 2-chunk lookahead),
// 2 CTAs/SM, fused BN-stat epilogue.  1/3 the MMAs of the bf16x3 version.
// ============================================================================
#define LDA        40
#define TILE_B     (128 * LDA)             // one operand tile (fp16 elems)
#define STAGE_E    (2 * TILE_B)            // A, B
#define STAGE_BYTES (STAGE_E * 2)          // 20480
#define SMEM2_BYTES (2 * STAGE_BYTES)      // 40960

__device__ __forceinline__ void issue_chunk(uint32_t sbase, int mrow0, int n0,
                                            int kc, int arow, int acol) {
    const size_t ga = (size_t)(mrow0 + arow) * KDIM + kc * 32 + acol;
    const size_t gw = (size_t)(n0 + arow) * KDIM + kc * 32 + acol;
    const uint32_t off = (uint32_t)(arow * LDA + acol) * 2;
    cp_async16(sbase + off,                     g_a + ga);
    cp_async16(sbase + off + 16,                g_a + ga + 8);
    cp_async16(sbase + TILE_B * 2 + off,        g_w + gw);
    cp_async16(sbase + TILE_B * 2 + off + 16,   g_w + gw + 8);
}

__global__ __launch_bounds__(256, 2) void k_gemm(const float* __restrict__ Vb,
                                                 const float* __restrict__ Ub) {
    extern __shared__ __align__(128) __half sm[];
    __shared__ float sBias[256];
    __shared__ float sred[24];

    const int tid  = threadIdx.x;
    const int wid  = tid >> 5;
    const int lane = tid & 31;

    const int ntile = blockIdx.x & 3;
    const int mtile = blockIdx.x >> 2;
    const int mrow0 = mtile * 128;
    const int n0    = ntile * 128;

    const int wm = (wid & 3) * 32;
    const int wn = (wid >> 2) * 64;

    for (int i = tid; i < 128; i += 256) {
        sBias[i]       = Vb[n0 + i];
        sBias[128 + i] = Ub[n0 + i];
    }
    if (tid < 24) sred[tid] = 0.f;

    float acc[2][8][4];
    #pragma unroll
    for (int mi = 0; mi < 2; mi++)
        #pragma unroll
        for (int nb = 0; nb < 8; nb++)
            #pragma unroll
            for (int q = 0; q < 4; q++) acc[mi][nb][q] = 0.f;

    const int arow = tid >> 1;
    const int acol = (tid & 1) * 16;
    const uint32_t sm_addr = smem_u32(sm);

    issue_chunk(sm_addr, mrow0, n0, 0, arow, acol);
    CP_COMMIT();
    issue_chunk(sm_addr + STAGE_BYTES, mrow0, n0, 1, arow, acol);
    CP_COMMIT();

    #pragma unroll 1
    for (int kc = 0; kc < 32; kc++) {
        CP_WAIT1();
        __syncthreads();

        {
            const uint32_t sA = sm_addr + (uint32_t)(kc & 1) * STAGE_BYTES;
            const uint32_t sB = sA + TILE_B * 2;

            #pragma unroll
            for (int ks = 0; ks < 2; ks++) {
                const int k0 = ks * 16;
                uint32_t aF[2][4];
                const int afr = lane & 15;
                const int afc = k0 + (lane >> 4) * 8;
                #pragma unroll
                for (int mi = 0; mi < 2; mi++) {
                    uint32_t ad = (uint32_t)((wm + mi * 16 + afr) * LDA + afc) * 2;
                    ldsm_x4(aF[mi], sA + ad);
                }
                #pragma unroll
                for (int g = 0; g < 2; g++) {
                    uint32_t bF[4][2];
                    #pragma unroll
                    for (int nq = 0; nq < 4; nq++) {
                        const int nb = g * 4 + nq;
                        const int brow = wn + nb * 8 + (lane & 7);
                        const int bcol = k0 + ((lane >> 3) & 1) * 8;
                        uint32_t bd = (uint32_t)(brow * LDA + bcol) * 2;
                        ldsm_x2(bF[nq], sB + bd);
                    }
                    #pragma unroll
                    for (int nq = 0; nq < 4; nq++)
                        #pragma unroll
                        for (int mi = 0; mi < 2; mi++)
                            mma_f16(acc[mi][g * 4 + nq], aF[mi], bF[nq]);
                }
            }
        }
        __syncthreads();

        const int kn = kc + 2;
        if (kn < 32)
            issue_chunk(sm_addr + (uint32_t)(kc & 1) * STAGE_BYTES, mrow0, n0, kn, arow, acol);
        CP_COMMIT();
    }

    // ---- epilogue: bias + write h (fp16) + fused BN stats (fp32) ----
    const int l4 = lane >> 2;
    const int lc = (lane & 3) * 2;

    #pragma unroll
    for (int mi = 0; mi < 2; mi++) {
        #pragma unroll
        for (int rr = 0; rr < 2; rr++) {
            const int row = wm + mi * 16 + rr * 8 + l4;
            const size_t grow = (size_t)mrow0 + row;
            const float rsv = g_rs[grow];
            __half* hrow = g_h + grow * CDIM + n0;
            float lsum = 0.f, lsq = 0.f;
            #pragma unroll
            for (int nb = 0; nb < 8; nb++) {
                const int c = wn + nb * 8 + lc;
                float v0 = acc[mi][nb][rr * 2 + 0] + rsv * sBias[c]     + sBias[128 + c];
                float v1 = acc[mi][nb][rr * 2 + 1] + rsv * sBias[c + 1] + sBias[128 + c + 1];
                lsum += v0 + v1;
                lsq  += v0 * v0 + v1 * v1;
                *reinterpret_cast<__half2*>(hrow + c) = __floats2half2_rn(v0, v1);
            }
            lsum += __shfl_xor_sync(0xFFFFFFFF, lsum, 1);
            lsq  += __shfl_xor_sync(0xFFFFFFFF, lsq, 1);
            lsum += __shfl_xor_sync(0xFFFFFFFF, lsum, 2);
            lsq  += __shfl_xor_sync(0xFFFFFFFF, lsq, 2);
            if ((lane & 3) == 0) {
                int node = (int)(grow % NNODE);
                atomicAdd(&sred[node], lsum);
                atomicAdd(&sred[12 + node], lsq);
            }
        }
    }
    __syncthreads();
    if (tid < NNODE) {
        atomicAdd(&g_sum[tid], sred[tid]);
        atomicAdd(&g_sumsq[tid], sred[12 + tid]);
    }
}

// ============================================================================
// Kernel 3: finalize BN stats
// ============================================================================
__global__ void k_finalize(const float* __restrict__ gamma, const float* __restrict__ beta) {
    int t = threadIdx.x;
    if (t < NNODE) {
        const float inv_n = 1.0f / ((float)NB * (float)CDIM);
        float mean = g_sum[t] * inv_n;
        float var  = g_sumsq[t] * inv_n - mean * mean;
        var = fmaxf(var, 0.f);
        float sc = gamma[t] * rsqrtf(var + BN_EPS);
        g_scale[t] = sc;
        g_shift[t] = beta[t] - mean * sc;
    }
}

// ============================================================================
// Kernel 4: out = relu(x + h*scale + shift)   (8 elems/thread, h fp16)
// ============================================================================
__global__ __launch_bounds__(512) void k_output(const float* __restrict__ x,
                                                float* __restrict__ out) {
    const size_t g8 = (size_t)blockIdx.x * 512 + threadIdx.x;
    const uint4 hraw = reinterpret_cast<const uint4*>(g_h)[g8];
    const float4 xv0 = reinterpret_cast<const float4*>(x)[g8 * 2];
    const float4 xv1 = reinterpret_cast<const float4*>(x)[g8 * 2 + 1];
    const int node = (int)((g8 >> 6) % NNODE);
    const float sc = g_scale[node], sh = g_shift[node];

    float2 h0 = __half22float2(*reinterpret_cast<const __half2*>(&hraw.x));
    float2 h1 = __half22float2(*reinterpret_cast<const __half2*>(&hraw.y));
    float2 h2 = __half22float2(*reinterpret_cast<const __half2*>(&hraw.z));
    float2 h3 = __half22float2(*reinterpret_cast<const __half2*>(&hraw.w));

    float4 o0, o1;
    o0.x = fmaxf(fmaf(h0.x, sc, sh) + xv0.x, 0.f);
    o0.y = fmaxf(fmaf(h0.y, sc, sh) + xv0.y, 0.f);
    o0.z = fmaxf(fmaf(h1.x, sc, sh) + xv0.z, 0.f);
    o0.w = fmaxf(fmaf(h1.y, sc, sh) + xv0.w, 0.f);
    o1.x = fmaxf(fmaf(h2.x, sc, sh) + xv1.x, 0.f);
    o1.y = fmaxf(fmaf(h2.y, sc, sh) + xv1.y, 0.f);
    o1.z = fmaxf(fmaf(h3.x, sc, sh) + xv1.z, 0.f);
    o1.w = fmaxf(fmaf(h3.y, sc, sh) + xv1.w, 0.f);
    reinterpret_cast<float4*>(out)[g8 * 2]     = o0;
    reinterpret_cast<float4*>(out)[g8 * 2 + 1] = o1;
}

// ============================================================================
// Launch
// ============================================================================
extern "C" void kernel_launch(void* const* d_in, const int* in_sizes, int n_in,
                              void* d_out, int out_size) {
    const float* x     = (const float*)d_in[0];
    const float* Uw    = (const float*)d_in[1];
    const float* Ub    = (const float*)d_in[2];
    const float* Vw    = (const float*)d_in[3];
    const float* Vb    = (const float*)d_in[4];
    const float* gamma = (const float*)d_in[5];
    const float* beta  = (const float*)d_in[6];
    float* out = (float*)d_out;

    cudaFuncSetAttribute(k_gemm, cudaFuncAttributeMaxDynamicSharedMemorySize, SMEM2_BYTES);

    k_zero_stats<<<1, 32>>>();
    k_prep_w<<<(NDIM * KDIM + 255) / 256, 256>>>(Uw, Vw);
    k_adjacency<<<NB, 128>>>(x);
    k_gemm<<<(ROWS / 128) * 4, 256, SMEM2_BYTES>>>(Vb, Ub);
    k_finalize<<<1, 32>>>(gamma, beta);
    k_output<<<(unsigned)((size_t)ROWS * CDIM / 8 / 512), 512>>>(x, out);
}

// round 14
// speedup vs baseline: 4.1371x; 1.0491x over previous
#include <cuda_runtime.h>
#include <cuda_bf16.h>
#include <cuda_fp16.h>
#include <cstdint>

// ============================================================================
// Problem constants
// ============================================================================
#define NB     16384
#define NNODE  12
#define CDIM   512
#define SXLD   (CDIM + 4)      // padded smem row (bank-conflict fix)
#define ROWS   (NB * NNODE)
#define KDIM   1024
#define NDIM   512
#define TOPK   4
#define BN_EPS 1e-5f

// ============================================================================
// Helpers (baseline PTX only)
// ============================================================================
__device__ __forceinline__ uint32_t smem_u32(const void* p) {
    uint32_t a;
    asm("{ .reg .u64 t; cvta.to.shared.u64 t, %1; cvt.u32.u64 %0, t; }" : "=r"(a) : "l"(p));
    return a;
}
__device__ __forceinline__ void ldsm_x4(uint32_t* r, uint32_t addr) {
    asm volatile("ldmatrix.sync.aligned.m8n8.x4.shared.b16 {%0,%1,%2,%3}, [%4];"
                 : "=r"(r[0]), "=r"(r[1]), "=r"(r[2]), "=r"(r[3]) : "r"(addr));
}
__device__ __forceinline__ void cp_async16(uint32_t saddr, const void* gaddr) {
    asm volatile("cp.async.cg.shared.global [%0], [%1], 16;" :: "r"(saddr), "l"(gaddr));
}
#define CP_COMMIT() asm volatile("cp.async.commit_group;" ::: "memory")
#define CP_WAIT1()  asm volatile("cp.async.wait_group 1;" ::: "memory")

// D += A * B^T : m16n8k16 row.col fp16 -> f32
__device__ __forceinline__ void mma_f16(float* d, const uint32_t* a, const uint32_t* b) {
    asm volatile(
        "mma.sync.aligned.m16n8k16.row.col.f32.f16.f16.f32 "
        "{%0,%1,%2,%3}, {%4,%5,%6,%7}, {%8,%9}, {%0,%1,%2,%3};"
        : "+f"(d[0]), "+f"(d[1]), "+f"(d[2]), "+f"(d[3])
        : "r"(a[0]), "r"(a[1]), "r"(a[2]), "r"(a[3]), "r"(b[0]), "r"(b[1]));
}

// ============================================================================
// Device scratch  (A operand + W + h all fp16)
// ============================================================================
__device__ __align__(16) __half g_a[(size_t)ROWS * KDIM];   // [y | x] fp16
__device__ __align__(16) __half g_w[(size_t)NDIM * KDIM];   // [Vw | Uw] fp16
__device__ __align__(16) __half g_h[(size_t)ROWS * CDIM];
__device__ float g_rs[ROWS];
__device__ float g_sum[NNODE];
__device__ float g_sumsq[NNODE];
__device__ float g_scale[NNODE];
__device__ float g_shift[NNODE];

// ============================================================================
// Kernel 0a
// ============================================================================
__global__ void k_zero_stats() {
    int t = threadIdx.x;
    if (t < NNODE) { g_sum[t] = 0.f; g_sumsq[t] = 0.f; }
}

// ============================================================================
// Kernel 0b: pack W = [Vw | Uw] as fp16
// ============================================================================
__global__ void k_prep_w(const float* __restrict__ Uw, const float* __restrict__ Vw) {
    int idx = blockIdx.x * blockDim.x + threadIdx.x;
    if (idx >= NDIM * KDIM) return;
    int d = idx >> 10;
    int k = idx & 1023;
    float v = (k < 512) ? Vw[d * 512 + k] : Uw[d * 512 + (k - 512)];
    g_w[idx] = __float2half_rn(v);
}

// ============================================================================
// Kernel 1: adjacency + aggregation -> A-operand rows [y | x] (fp16)
// ============================================================================
__global__ __launch_bounds__(128) void k_adjacency(const float* __restrict__ x) {
    __shared__ __align__(16) float sx[NNODE][SXLD];
    __shared__ float ssim[NNODE][NNODE];
    __shared__ float sA[NNODE][NNODE];
    __shared__ float sthr[NNODE];
    __shared__ float sdinv[NNODE];

    const int tid = threadIdx.x;
    const int b   = blockIdx.x;

    {
        const float4* src = reinterpret_cast<const float4*>(x + (size_t)b * NNODE * CDIM);
        for (int u = tid; u < NNODE * CDIM / 4; u += 128) {
            int i = u >> 7;
            int q = u & 127;
            *reinterpret_cast<float4*>(&sx[i][q * 4]) = src[u];
        }
    }
    __syncthreads();

    if (tid < 78) {
        int i = 0, t = tid;
        while (t >= NNODE - i) { t -= NNODE - i; i++; }
        int j = i + t;
        float a0 = 0.f, a1 = 0.f, a2 = 0.f, a3 = 0.f;
        #pragma unroll 4
        for (int c = 0; c < CDIM; c += 4) {
            float4 a  = *reinterpret_cast<const float4*>(&sx[i][c]);
            float4 bb = *reinterpret_cast<const float4*>(&sx[j][c]);
            a0 += a.x * bb.x; a1 += a.y * bb.y;
            a2 += a.z * bb.z; a3 += a.w * bb.w;
        }
        float acc = (a0 + a1) + (a2 + a3);
        ssim[i][j] = acc;
        ssim[j][i] = acc;
    }
    __syncthreads();

    if (tid < NNODE) {
        float v[NNODE];
        #pragma unroll
        for (int j = 0; j < NNODE; j++) v[j] = ssim[tid][j];
        float thr = 0.f;
        #pragma unroll
        for (int t = 0; t < TOPK; t++) {
            int m = 0;
            float mv = v[0];
            #pragma unroll
            for (int j = 1; j < NNODE; j++) if (v[j] > mv) { mv = v[j]; m = j; }
            thr = mv;
            v[m] = -3.4e38f;
        }
        sthr[tid] = thr;
        int deg = 0;
        #pragma unroll
        for (int j = 0; j < NNODE; j++) deg += (ssim[tid][j] >= thr) ? 1 : 0;
        sdinv[tid] = rsqrtf((float)deg);
    }
    __syncthreads();

    for (int t = tid; t < NNODE * NNODE; t += 128) {
        int i = t / NNODE, j = t % NNODE;
        float adj = (ssim[i][j] >= sthr[i]) ? 1.f : 0.f;
        sA[i][j] = sdinv[i] * sdinv[j] * adj;
    }
    __syncthreads();

    if (tid < NNODE) {
        float rs = 0.f;
        #pragma unroll
        for (int j = 0; j < NNODE; j++) rs += sA[tid][j];
        g_rs[(size_t)b * NNODE + tid] = rs;
    }

    // y = A @ x -> cols [0,512) fp16
    {
        const int c0 = tid * 4;
        float4 xv[NNODE];
        #pragma unroll
        for (int j = 0; j < NNODE; j++)
            xv[j] = *reinterpret_cast<const float4*>(&sx[j][c0]);
        #pragma unroll
        for (int i = 0; i < NNODE; i++) {
            float a0 = 0.f, a1 = 0.f, a2 = 0.f, a3 = 0.f;
            #pragma unroll
            for (int j = 0; j < NNODE; j++) {
                float w = sA[i][j];
                a0 += w * xv[j].x; a1 += w * xv[j].y;
                a2 += w * xv[j].z; a3 += w * xv[j].w;
            }
            size_t o = ((size_t)b * NNODE + i) * KDIM + c0;
            __half2 p0 = __floats2half2_rn(a0, a1);
            __half2 p1 = __floats2half2_rn(a2, a3);
            *reinterpret_cast<__half2*>(g_a + o)     = p0;
            *reinterpret_cast<__half2*>(g_a + o + 2) = p1;
        }
    }

    // x -> cols [512,1024) fp16
    for (int u = tid; u < NNODE * 128; u += 128) {
        int i = u >> 7, q = u & 127;
        float4 v = *reinterpret_cast<const float4*>(&sx[i][q * 4]);
        size_t o = ((size_t)b * NNODE + i) * KDIM + 512 + q * 4;
        __half2 p0 = __floats2half2_rn(v.x, v.y);
        __half2 p1 = __floats2half2_rn(v.z, v.w);
        *reinterpret_cast<__half2*>(g_a + o)     = p0;
        *reinterpret_cast<__half2*>(g_a + o + 2) = p1;
    }
}

// ============================================================================
// Kernel 2: GEMM  h = [y|x] @ Wcat^T + rs*Vb + Ub   (fp16 single-term HMMA)
// R13 structure; B fragments via ldsm_x4 (2 nb per issue) -> 12 LDSM/warp/chunk
// ============================================================================
#define LDA        40
#define TILE_B     (128 * LDA)             // one operand tile (fp16 elems)
#define STAGE_E    (2 * TILE_B)            // A, B
#define STAGE_BYTES (STAGE_E * 2)          // 20480
#define SMEM2_BYTES (2 * STAGE_BYTES)      // 40960

__device__ __forceinline__ void issue_chunk(uint32_t sbase, int mrow0, int n0,
                                            int kc, int arow, int acol) {
    const size_t ga = (size_t)(mrow0 + arow) * KDIM + kc * 32 + acol;
    const size_t gw = (size_t)(n0 + arow) * KDIM + kc * 32 + acol;
    const uint32_t off = (uint32_t)(arow * LDA + acol) * 2;
    cp_async16(sbase + off,                     g_a + ga);
    cp_async16(sbase + off + 16,                g_a + ga + 8);
    cp_async16(sbase + TILE_B * 2 + off,        g_w + gw);
    cp_async16(sbase + TILE_B * 2 + off + 16,   g_w + gw + 8);
}

__global__ __launch_bounds__(256, 2) void k_gemm(const float* __restrict__ Vb,
                                                 const float* __restrict__ Ub) {
    extern __shared__ __align__(128) __half sm[];
    __shared__ float sBias[256];
    __shared__ float sred[24];

    const int tid  = threadIdx.x;
    const int wid  = tid >> 5;
    const int lane = tid & 31;

    const int ntile = blockIdx.x & 3;
    const int mtile = blockIdx.x >> 2;
    const int mrow0 = mtile * 128;
    const int n0    = ntile * 128;

    const int wm = (wid & 3) * 32;
    const int wn = (wid >> 2) * 64;

    for (int i = tid; i < 128; i += 256) {
        sBias[i]       = Vb[n0 + i];
        sBias[128 + i] = Ub[n0 + i];
    }
    if (tid < 24) sred[tid] = 0.f;

    float acc[2][8][4];
    #pragma unroll
    for (int mi = 0; mi < 2; mi++)
        #pragma unroll
        for (int nb = 0; nb < 8; nb++)
            #pragma unroll
            for (int q = 0; q < 4; q++) acc[mi][nb][q] = 0.f;

    const int arow = tid >> 1;
    const int acol = (tid & 1) * 16;
    const uint32_t sm_addr = smem_u32(sm);

    issue_chunk(sm_addr, mrow0, n0, 0, arow, acol);
    CP_COMMIT();
    issue_chunk(sm_addr + STAGE_BYTES, mrow0, n0, 1, arow, acol);
    CP_COMMIT();

    #pragma unroll 1
    for (int kc = 0; kc < 32; kc++) {
        CP_WAIT1();
        __syncthreads();

        {
            const uint32_t sA = sm_addr + (uint32_t)(kc & 1) * STAGE_BYTES;
            const uint32_t sB = sA + TILE_B * 2;

            #pragma unroll
            for (int ks = 0; ks < 2; ks++) {
                const int k0 = ks * 16;
                uint32_t aF[2][4];
                const int afr = lane & 15;
                const int afc = k0 + (lane >> 4) * 8;
                #pragma unroll
                for (int mi = 0; mi < 2; mi++) {
                    uint32_t ad = (uint32_t)((wm + mi * 16 + afr) * LDA + afc) * 2;
                    ldsm_x4(aF[mi], sA + ad);
                }
                // B fragments for 8 nb via 4 ldsm_x4 (2 nb each):
                // quad=lane>>3: (quad>>1)=nb-within-pair row-group, (quad&1)=k-half
                uint32_t bF[8][2];
                const int quad = lane >> 3;
                const int rsel = (quad >> 1) * 8 + (lane & 7);
                const int csel = k0 + (quad & 1) * 8;
                #pragma unroll
                for (int np = 0; np < 4; np++) {
                    const int brow = wn + (np * 2) * 8 + rsel;
                    uint32_t bd = (uint32_t)(brow * LDA + csel) * 2;
                    uint32_t r[4];
                    ldsm_x4(r, sB + bd);
                    bF[np*2][0]   = r[0]; bF[np*2][1]   = r[1];
                    bF[np*2+1][0] = r[2]; bF[np*2+1][1] = r[3];
                }
                #pragma unroll
                for (int nb = 0; nb < 8; nb++)
                    #pragma unroll
                    for (int mi = 0; mi < 2; mi++)
                        mma_f16(acc[mi][nb], aF[mi], bF[nb]);
            }
        }
        __syncthreads();

        const int kn = kc + 2;
        if (kn < 32)
            issue_chunk(sm_addr + (uint32_t)(kc & 1) * STAGE_BYTES, mrow0, n0, kn, arow, acol);
        CP_COMMIT();
    }

    // ---- epilogue: bias + write h (fp16) + fused BN stats (fp32) ----
    const int l4 = lane >> 2;
    const int lc = (lane & 3) * 2;

    #pragma unroll
    for (int mi = 0; mi < 2; mi++) {
        #pragma unroll
        for (int rr = 0; rr < 2; rr++) {
            const int row = wm + mi * 16 + rr * 8 + l4;
            const size_t grow = (size_t)mrow0 + row;
            const float rsv = g_rs[grow];
            __half* hrow = g_h + grow * CDIM + n0;
            float lsum = 0.f, lsq = 0.f;
            #pragma unroll
            for (int nb = 0; nb < 8; nb++) {
                const int c = wn + nb * 8 + lc;
                float v0 = acc[mi][nb][rr * 2 + 0] + rsv * sBias[c]     + sBias[128 + c];
                float v1 = acc[mi][nb][rr * 2 + 1] + rsv * sBias[c + 1] + sBias[128 + c + 1];
                lsum += v0 + v1;
                lsq  += v0 * v0 + v1 * v1;
                *reinterpret_cast<__half2*>(hrow + c) = __floats2half2_rn(v0, v1);
            }
            lsum += __shfl_xor_sync(0xFFFFFFFF, lsum, 1);
            lsq  += __shfl_xor_sync(0xFFFFFFFF, lsq, 1);
            lsum += __shfl_xor_sync(0xFFFFFFFF, lsum, 2);
            lsq  += __shfl_xor_sync(0xFFFFFFFF, lsq, 2);
            if ((lane & 3) == 0) {
                int node = (int)(grow % NNODE);
                atomicAdd(&sred[node], lsum);
                atomicAdd(&sred[12 + node], lsq);
            }
        }
    }
    __syncthreads();
    if (tid < NNODE) {
        atomicAdd(&g_sum[tid], sred[tid]);
        atomicAdd(&g_sumsq[tid], sred[12 + tid]);
    }
}

// ============================================================================
// Kernel 3: finalize BN stats
// ============================================================================
__global__ void k_finalize(const float* __restrict__ gamma, const float* __restrict__ beta) {
    int t = threadIdx.x;
    if (t < NNODE) {
        const float inv_n = 1.0f / ((float)NB * (float)CDIM);
        float mean = g_sum[t] * inv_n;
        float var  = g_sumsq[t] * inv_n - mean * mean;
        var = fmaxf(var, 0.f);
        float sc = gamma[t] * rsqrtf(var + BN_EPS);
        g_scale[t] = sc;
        g_shift[t] = beta[t] - mean * sc;
    }
}

// ============================================================================
// Kernel 4: out = relu(x + h*scale + shift)   (8 elems/thread, h fp16)
// ============================================================================
__global__ __launch_bounds__(512) void k_output(const float* __restrict__ x,
                                                float* __restrict__ out) {
    const size_t g8 = (size_t)blockIdx.x * 512 + threadIdx.x;
    const uint4 hraw = reinterpret_cast<const uint4*>(g_h)[g8];
    const float4 xv0 = reinterpret_cast<const float4*>(x)[g8 * 2];
    const float4 xv1 = reinterpret_cast<const float4*>(x)[g8 * 2 + 1];
    const int node = (int)((g8 >> 6) % NNODE);
    const float sc = g_scale[node], sh = g_shift[node];

    float2 h0 = __half22float2(*reinterpret_cast<const __half2*>(&hraw.x));
    float2 h1 = __half22float2(*reinterpret_cast<const __half2*>(&hraw.y));
    float2 h2 = __half22float2(*reinterpret_cast<const __half2*>(&hraw.z));
    float2 h3 = __half22float2(*reinterpret_cast<const __half2*>(&hraw.w));

    float4 o0, o1;
    o0.x = fmaxf(fmaf(h0.x, sc, sh) + xv0.x, 0.f);
    o0.y = fmaxf(fmaf(h0.y, sc, sh) + xv0.y, 0.f);
    o0.z = fmaxf(fmaf(h1.x, sc, sh) + xv0.z, 0.f);
    o0.w = fmaxf(fmaf(h1.y, sc, sh) + xv0.w, 0.f);
    o1.x = fmaxf(fmaf(h2.x, sc, sh) + xv1.x, 0.f);
    o1.y = fmaxf(fmaf(h2.y, sc, sh) + xv1.y, 0.f);
    o1.z = fmaxf(fmaf(h3.x, sc, sh) + xv1.z, 0.f);
    o1.w = fmaxf(fmaf(h3.y, sc, sh) + xv1.w, 0.f);
    reinterpret_cast<float4*>(out)[g8 * 2]     = o0;
    reinterpret_cast<float4*>(out)[g8 * 2 + 1] = o1;
}

// ============================================================================
// Launch
// ============================================================================
extern "C" void kernel_launch(void* const* d_in, const int* in_sizes, int n_in,
                              void* d_out, int out_size) {
    const float* x     = (const float*)d_in[0];
    const float* Uw    = (const float*)d_in[1];
    const float* Ub    = (const float*)d_in[2];
    const float* Vw    = (const float*)d_in[3];
    const float* Vb    = (const float*)d_in[4];
    const float* gamma = (const float*)d_in[5];
    const float* beta  = (const float*)d_in[6];
    float* out = (float*)d_out;

    cudaFuncSetAttribute(k_gemm, cudaFuncAttributeMaxDynamicSharedMemorySize, SMEM2_BYTES);

    k_zero_stats<<<1, 32>>>();
    k_prep_w<<<(NDIM * KDIM + 255) / 256, 256>>>(Uw, Vw);
    k_adjacency<<<NB, 128>>>(x);
    k_gemm<<<(ROWS / 128) * 4, 256, SMEM2_BYTES>>>(Vb, Ub);
    k_finalize<<<1, 32>>>(gamma, beta);
    k_output<<<(unsigned)((size_t)ROWS * CDIM / 8 / 512), 512>>>(x, out);
}